// round 14
// baseline (speedup 1.0000x reference)
#include <cuda_runtime.h>
#include <cuda_bf16.h>

// RobustPrompt_I: graph prompt + edge pruning
//  in: x[N,128] f32, edge_index[2,E] i32, p_sim[1,128], p_deg[1,128], p_other[1,128]
//  out: x_new[N,128] f32  ++  keep[E] (0/1 as f32)

#define D        128
#define D4       32
#define NCAP     131072
#define ECAP     1048576
#define SIM_THR  0.2f
#define DEG_THR  3.0f
#define PT_THR   0.1f
#define EPSV     1e-8f

#define BSHIFT   6                    // bucket = r >> 6 (64 rows = 32KB)
#define BROWS    64
#define MAXBUCK  2048
#define BCAP     1024                 // slots/bucket (mean ~410, +30 sigma)
#define OVCAP    131072
#define OVB      64

__device__ float2 g_cd[NCAP];         // (SUM(dot*rinv_r), deg) per node
__device__ float4 g_A0[NCAP];         // (d0, d1, d2, ||x||^2)
__device__ float4 g_rec16[NCAP];      // (H0, H1, H2, s[LSBs=combo])
__device__ float  g_dot[ECAP];        // raw dot per edge
__device__ int    g_cnt[MAXBUCK];
__device__ int3   g_pedge[MAXBUCK * BCAP];
__device__ int    g_ovfcnt;
__device__ int3   g_ovf[OVCAP];
__device__ float  g_W[4][4];
__device__ float  g_GC[4][4];
__device__ float  g_GV[4][4];
__device__ float4 g_delta[4][D4];

// ---------- setup body (1 warp) ----------
__device__ __forceinline__ void setup_body(const float* __restrict__ ps,
                                           const float* __restrict__ pd,
                                           const float* __restrict__ po,
                                           int lane) {
    unsigned full = 0xFFFFFFFFu;
    float4 P[3];
    P[0] = reinterpret_cast<const float4*>(ps)[lane];
    P[1] = reinterpret_cast<const float4*>(pd)[lane];
    P[2] = reinterpret_cast<const float4*>(po)[lane];

    int nz[3];
    #pragma unroll
    for (int k = 0; k < 3; k++) {
        bool z = (P[k].x != 0.f) & (P[k].y != 0.f) & (P[k].z != 0.f) & (P[k].w != 0.f);
        nz[k] = __all_sync(full, z);
    }
    float G[3][3];
    #pragma unroll
    for (int a = 0; a < 3; a++)
        #pragma unroll
        for (int b = 0; b < 3; b++) {
            float s = P[a].x * P[b].x + P[a].y * P[b].y + P[a].z * P[b].z + P[a].w * P[b].w;
            #pragma unroll
            for (int o = 16; o > 0; o >>= 1) s += __shfl_xor_sync(full, s, o);
            G[a][b] = s;
        }
    float W[4][3];
    #pragma unroll
    for (int idx = 0; idx < 4; idx++) {
        int msim = idx & 1, mdeg = (idx >> 1) & 1, moth = (idx == 0);
        int plen = msim * nz[0] + mdeg * nz[1] + moth * nz[2];
        float inv = (plen > 0) ? (1.0f / (float)plen) : 0.0f;
        W[idx][0] = (float)msim * inv;
        W[idx][1] = (float)mdeg * inv;
        W[idx][2] = (float)moth * inv;
        float4 dl;
        dl.x = W[idx][0]*P[0].x + W[idx][1]*P[1].x + W[idx][2]*P[2].x;
        dl.y = W[idx][0]*P[0].y + W[idx][1]*P[1].y + W[idx][2]*P[2].y;
        dl.z = W[idx][0]*P[0].z + W[idx][1]*P[1].z + W[idx][2]*P[2].z;
        dl.w = W[idx][0]*P[0].w + W[idx][1]*P[1].w + W[idx][2]*P[2].w;
        g_delta[idx][lane] = dl;
    }
    if (lane == 0) {
        for (int idx = 0; idx < 4; idx++) {
            g_W[idx][0] = W[idx][0]; g_W[idx][1] = W[idx][1];
            g_W[idx][2] = W[idx][2]; g_W[idx][3] = 0.f;
            for (int k = 0; k < 3; k++)
                g_GV[idx][k] = G[k][0]*W[idx][0] + G[k][1]*W[idx][1] + G[k][2]*W[idx][2];
            g_GV[idx][3] = 0.f;
        }
        for (int a = 0; a < 4; a++)
            for (int b = 0; b < 4; b++) {
                float s = 0.f;
                for (int k = 0; k < 3; k++)
                    for (int j = 0; j < 3; j++)
                        s += W[a][k] * G[k][j] * W[b][j];
                g_GC[a][b] = s;
            }
    }
}

// ---------- K1: edge scatter-to-buckets | setup | node stats ----------
__global__ void prep_kernel(const float* __restrict__ x,
                            const int* __restrict__ ei,
                            const float* __restrict__ ps,
                            const float* __restrict__ pd,
                            const float* __restrict__ po,
                            int n, int E, int NS) {
    int bid = blockIdx.x;
    if (bid < NS) {
        int e = bid * blockDim.x + threadIdx.x;
        if (e >= E) return;
        int r = __ldg(&ei[e]);
        int c = __ldg(&ei[E + e]);
        int b = r >> BSHIFT;
        int pos = atomicAdd(&g_cnt[b], 1);
        if (pos < BCAP) g_pedge[b * BCAP + pos] = make_int3(r, c, e);
        else {
            int op = atomicAdd(&g_ovfcnt, 1);
            if (op < OVCAP) g_ovf[op] = make_int3(r, c, e);
        }
    } else if (bid == NS) {
        if (threadIdx.x < 32) setup_body(ps, pd, po, threadIdx.x);
    } else {
        int w    = ((bid - NS - 1) * blockDim.x + threadIdx.x) >> 5;
        int lane = threadIdx.x & 31;
        if (w >= n) return;
        const float4* X = reinterpret_cast<const float4*>(x);
        float4 xv = X[(size_t)w * D4 + lane];
        float4 P0 = reinterpret_cast<const float4*>(ps)[lane];
        float4 P1 = reinterpret_cast<const float4*>(pd)[lane];
        float4 P2 = reinterpret_cast<const float4*>(po)[lane];

        float ss = xv.x*xv.x + xv.y*xv.y + xv.z*xv.z + xv.w*xv.w;
        float d0 = xv.x*P0.x + xv.y*P0.y + xv.z*P0.z + xv.w*P0.w;
        float d1 = xv.x*P1.x + xv.y*P1.y + xv.z*P1.z + xv.w*P1.w;
        float d2 = xv.x*P2.x + xv.y*P2.y + xv.z*P2.z + xv.w*P2.w;
        #pragma unroll
        for (int o = 16; o > 0; o >>= 1) {
            ss += __shfl_xor_sync(0xFFFFFFFFu, ss, o);
            d0 += __shfl_xor_sync(0xFFFFFFFFu, d0, o);
            d1 += __shfl_xor_sync(0xFFFFFFFFu, d1, o);
            d2 += __shfl_xor_sync(0xFFFFFFFFu, d2, o);
        }
        if (lane == 0) g_A0[w] = make_float4(d0, d1, d2, ss);
    }
}

// ---------- K2: bucketed edge pass — r-rows staged in SMEM, c-rows from L2 ----------
__global__ void __launch_bounds__(512) edge_kernel(const float* __restrict__ x,
                                                   int nbuck, int n) {
    __shared__ float4 sx[BROWS * D4];   // 32 KB: this bucket's 64 r-rows
    const float4* X = reinterpret_cast<const float4*>(x);
    int b   = blockIdx.x;
    int sub = threadIdx.x & 7;

    if (b < nbuck) {
        int base = b << BSHIFT;
        int rows = min(BROWS, n - base);
        const float4* Xb = X + (size_t)base * D4;
        for (int i = threadIdx.x; i < rows * D4; i += 512) sx[i] = Xb[i];
        __syncthreads();

        int cnt = min(g_cnt[b], BCAP);
        const int3* src = &g_pedge[(size_t)b * BCAP];
        for (int i = threadIdx.x >> 3; i < cnt; i += 64) {
            int3 rec = src[i];
            const float4* Ar = &sx[(rec.x - base) * D4 + sub];
            const float4* Bc = X + (size_t)rec.y * D4 + sub;
            float4 a[4], bb[4];
            #pragma unroll
            for (int k = 0; k < 4; k++) bb[k] = __ldg(Bc + 8 * k);
            #pragma unroll
            for (int k = 0; k < 4; k++) a[k] = Ar[8 * k];

            float s = 0.f, nr = 0.f;
            #pragma unroll
            for (int k = 0; k < 4; k++) {
                s  += a[k].x*bb[k].x + a[k].y*bb[k].y + a[k].z*bb[k].z + a[k].w*bb[k].w;
                nr += a[k].x*a[k].x + a[k].y*a[k].y + a[k].z*a[k].z + a[k].w*a[k].w;
            }
            #pragma unroll
            for (int o = 4; o > 0; o >>= 1) {
                s  += __shfl_xor_sync(0xFFFFFFFFu, s,  o);
                nr += __shfl_xor_sync(0xFFFFFFFFu, nr, o);
            }
            if (sub == 0) {
                g_dot[rec.z] = s;
                atomicAdd(&g_cd[rec.y].x, s * rsqrtf(nr));
                atomicAdd(&g_cd[rec.y].y, 1.0f);
            }
        }
    } else {
        // overflow backstop: r from global
        int cnt = min(g_ovfcnt, OVCAP);
        for (int i = (b - nbuck) * 64 + (threadIdx.x >> 3); i < cnt; i += OVB * 64) {
            int3 rec = g_ovf[i];
            const float4* Ar = X + (size_t)rec.x * D4 + sub;
            const float4* Bc = X + (size_t)rec.y * D4 + sub;
            float4 a[4], bb[4];
            #pragma unroll
            for (int k = 0; k < 4; k++) a[k] = __ldg(Ar + 8 * k);
            #pragma unroll
            for (int k = 0; k < 4; k++) bb[k] = __ldg(Bc + 8 * k);
            float s = 0.f, nr = 0.f;
            #pragma unroll
            for (int k = 0; k < 4; k++) {
                s  += a[k].x*bb[k].x + a[k].y*bb[k].y + a[k].z*bb[k].z + a[k].w*bb[k].w;
                nr += a[k].x*a[k].x + a[k].y*a[k].y + a[k].z*a[k].z + a[k].w*a[k].w;
            }
            #pragma unroll
            for (int o = 4; o > 0; o >>= 1) {
                s  += __shfl_xor_sync(0xFFFFFFFFu, s,  o);
                nr += __shfl_xor_sync(0xFFFFFFFFu, nr, o);
            }
            if (sub == 0) {
                g_dot[rec.z] = s;
                atomicAdd(&g_cd[rec.y].x, s * rsqrtf(nr));
                atomicAdd(&g_cd[rec.y].y, 1.0f);
            }
        }
    }
}

// ---------- combo2 (thread/node) ----------
__global__ void combo2_kernel(int n) {
    int i = blockIdx.x * blockDim.x + threadIdx.x;
    if (i >= n) return;
    float2 cd = g_cd[i];
    float4 A  = g_A0[i];

    float rinv_c = rsqrtf(A.w);
    float csum = cd.x * rinv_c;
    float deg  = cd.y;

    bool msim = (deg > 0.f) && ((csum / deg) <= SIM_THR);
    bool mdeg = (deg <= DEG_THR);
    int c = (int)msim | ((int)mdeg << 1);

    float4 Wc = *reinterpret_cast<const float4*>(&g_W[c][0]);
    float4 Gv = *reinterpret_cast<const float4*>(&g_GV[c][0]);
    float xdd = Wc.x*A.x + Wc.y*A.y + Wc.z*A.z;
    float nn2 = A.w + 2.0f * xdd + g_GC[c][c];
    float s = 1.0f / fmaxf(sqrtf(fmaxf(nn2, 0.f)), EPSV);

    unsigned su = (__float_as_uint(s) & ~3u) | (unsigned)c;
    float sp = __uint_as_float(su);

    g_rec16[i] = make_float4(sp * (A.x + 0.5f * Gv.x),
                             sp * (A.y + 0.5f * Gv.y),
                             sp * (A.z + 0.5f * Gv.z), sp);
}

// ---------- K3 finish: node write (MLP4) | edge2 (1 LDG.128/endpoint) ----------
__global__ void finish_kernel(const float* __restrict__ x,
                              const int* __restrict__ ei,
                              float* __restrict__ out,
                              float* __restrict__ keep,
                              int n, int E, int NBn) {
    if ((int)blockIdx.x < NBn) {
        int tid  = threadIdx.x;
        int node = blockIdx.x * 32 + (tid >> 3);
        if (node >= n) return;
        int j = tid & 7;
        int idx = (int)(__float_as_uint(g_rec16[node].w) & 3u);
        const float4* Xr = reinterpret_cast<const float4*>(x) + (size_t)node * D4;
        float4 xv0 = __ldcs(Xr + j);
        float4 xv1 = __ldcs(Xr + j + 8);
        float4 xv2 = __ldcs(Xr + j + 16);
        float4 xv3 = __ldcs(Xr + j + 24);
        float4 dl0 = g_delta[idx][j];
        float4 dl1 = g_delta[idx][j + 8];
        float4 dl2 = g_delta[idx][j + 16];
        float4 dl3 = g_delta[idx][j + 24];
        xv0.x += dl0.x; xv0.y += dl0.y; xv0.z += dl0.z; xv0.w += dl0.w;
        xv1.x += dl1.x; xv1.y += dl1.y; xv1.z += dl1.z; xv1.w += dl1.w;
        xv2.x += dl2.x; xv2.y += dl2.y; xv2.z += dl2.z; xv2.w += dl2.w;
        xv3.x += dl3.x; xv3.y += dl3.y; xv3.z += dl3.z; xv3.w += dl3.w;
        float4* Or = reinterpret_cast<float4*>(out) + (size_t)node * D4;
        __stcs(Or + j,      xv0);
        __stcs(Or + j + 8,  xv1);
        __stcs(Or + j + 16, xv2);
        __stcs(Or + j + 24, xv3);
    } else {
        int t  = (blockIdx.x - NBn) * blockDim.x + threadIdx.x;
        int e0 = t * 2;
        int e1 = e0 + 1;
        if (e0 >= E) return;
        bool has1 = (e1 < E);

        int r0 = __ldg(&ei[e0]);
        int c0 = __ldg(&ei[E + e0]);
        int r1 = has1 ? __ldg(&ei[e1]) : r0;
        int c1 = has1 ? __ldg(&ei[E + e1]) : c0;
        float dt0 = g_dot[e0];
        float dt1 = has1 ? g_dot[e1] : 0.f;

        float4 R0 = g_rec16[r0], C0 = g_rec16[c0];
        float4 R1 = g_rec16[r1], C1 = g_rec16[c1];

        int cr0 = (int)(__float_as_uint(R0.w) & 3u);
        int cc0 = (int)(__float_as_uint(C0.w) & 3u);
        int cr1 = (int)(__float_as_uint(R1.w) & 3u);
        int cc1 = (int)(__float_as_uint(C1.w) & 3u);

        float4 Wr0 = *reinterpret_cast<const float4*>(&g_W[cr0][0]);
        float4 Wc0 = *reinterpret_cast<const float4*>(&g_W[cc0][0]);
        float4 Wr1 = *reinterpret_cast<const float4*>(&g_W[cr1][0]);
        float4 Wc1 = *reinterpret_cast<const float4*>(&g_W[cc1][0]);

        float cos0 = (R0.w * C0.w) * dt0
                   + C0.w * (R0.x*Wc0.x + R0.y*Wc0.y + R0.z*Wc0.z)
                   + R0.w * (C0.x*Wr0.x + C0.y*Wr0.y + C0.z*Wr0.z);
        keep[e0] = (cos0 >= PT_THR) ? 1.0f : 0.0f;
        if (has1) {
            float cos1 = (R1.w * C1.w) * dt1
                       + C1.w * (R1.x*Wc1.x + R1.y*Wc1.y + R1.z*Wc1.z)
                       + R1.w * (C1.x*Wr1.x + C1.y*Wr1.y + C1.z*Wr1.z);
            keep[e1] = (cos1 >= PT_THR) ? 1.0f : 0.0f;
        }
    }
}

extern "C" void kernel_launch(void* const* d_in, const int* in_sizes, int n_in,
                              void* d_out, int out_size) {
    const float* x  = (const float*)d_in[0];
    const int*   ei = (const int*)d_in[1];
    const float* ps = (const float*)d_in[2];
    const float* pd = (const float*)d_in[3];
    const float* po = (const float*)d_in[4];
    float* out = (float*)d_out;

    int N = in_sizes[0] / D;
    int E = in_sizes[1] / 2;
    int nbuck = (N + BROWS - 1) >> BSHIFT;
    if (nbuck > MAXBUCK) nbuck = MAXBUCK;

    static void* cd_ptr = nullptr;
    static void* cnt_ptr = nullptr;
    static void* ovf_ptr = nullptr;
    if (!cd_ptr)  cudaGetSymbolAddress(&cd_ptr,  g_cd);
    if (!cnt_ptr) cudaGetSymbolAddress(&cnt_ptr, g_cnt);
    if (!ovf_ptr) cudaGetSymbolAddress(&ovf_ptr, g_ovfcnt);
    cudaMemsetAsync(cd_ptr,  0, (size_t)N * sizeof(float2));
    cudaMemsetAsync(cnt_ptr, 0, (size_t)nbuck * sizeof(int));
    cudaMemsetAsync(ovf_ptr, 0, sizeof(int));

    int NS  = (E + 255) / 256;
    int NBa = (N + 7) / 8;
    prep_kernel<<<NS + 1 + NBa, 256>>>(x, ei, ps, pd, po, N, E, NS);

    edge_kernel<<<nbuck + OVB, 512>>>(x, nbuck, N);

    combo2_kernel<<<(N + 255) / 256, 256>>>(N);

    int NBn = (N + 31) / 32;
    bool do_keep = ((long long)out_size >= (long long)N * D + E);
    int NBe2 = do_keep ? ((E + 1) / 2 + 255) / 256 : 0;
    float* keep = out + (size_t)N * D;
    finish_kernel<<<NBn + NBe2, 256>>>(x, ei, out, keep, N, E, NBn);
}

// round 15
// speedup vs baseline: 1.6762x; 1.6762x over previous
#include <cuda_runtime.h>
#include <cuda_bf16.h>

// RobustPrompt_I: graph prompt + edge pruning
//  in: x[N,128] f32, edge_index[2,E] i32, p_sim[1,128], p_deg[1,128], p_other[1,128]
//  out: x_new[N,128] f32  ++  keep[E] (0/1 as f32)

#define D        128
#define D4       32
#define NCAP     131072
#define ECAP     1048576
#define SIM_THR  0.2f
#define DEG_THR  3.0f
#define PT_THR   0.1f
#define EPSV     1e-8f

#define NBE      2048        // persistent edge blocks in big_kernel

__device__ float2 g_cd[NCAP];      // (SUM(dot*rinv_r), deg) — zero-init BSS; re-zeroed by finish
__device__ float4 g_A0[NCAP];      // (d0, d1, d2, ||x||^2)
__device__ float4 g_rec16[NCAP];   // (H0, H1, H2, s[mantissa LSBs = combo])
__device__ float  g_dot[ECAP];     // raw dot per edge
__device__ float  g_W[4][4];       // combo -> weight triple (row=float4)
__device__ float  g_GC[4][4];      // delta_a · delta_b LUT
__device__ float  g_GV[4][4];      // G · W[c] per combo
__device__ float4 g_delta[4][D4];  // the 4 possible delta rows

// ---------- setup body (1 warp) ----------
__device__ __forceinline__ void setup_body(const float* __restrict__ ps,
                                           const float* __restrict__ pd,
                                           const float* __restrict__ po,
                                           int lane) {
    unsigned full = 0xFFFFFFFFu;
    float4 P[3];
    P[0] = reinterpret_cast<const float4*>(ps)[lane];
    P[1] = reinterpret_cast<const float4*>(pd)[lane];
    P[2] = reinterpret_cast<const float4*>(po)[lane];

    int nz[3];
    #pragma unroll
    for (int k = 0; k < 3; k++) {
        bool z = (P[k].x != 0.f) & (P[k].y != 0.f) & (P[k].z != 0.f) & (P[k].w != 0.f);
        nz[k] = __all_sync(full, z);
    }
    float G[3][3];
    #pragma unroll
    for (int a = 0; a < 3; a++)
        #pragma unroll
        for (int b = 0; b < 3; b++) {
            float s = P[a].x * P[b].x + P[a].y * P[b].y + P[a].z * P[b].z + P[a].w * P[b].w;
            #pragma unroll
            for (int o = 16; o > 0; o >>= 1) s += __shfl_xor_sync(full, s, o);
            G[a][b] = s;
        }
    float W[4][3];
    #pragma unroll
    for (int idx = 0; idx < 4; idx++) {
        int msim = idx & 1, mdeg = (idx >> 1) & 1, moth = (idx == 0);
        int plen = msim * nz[0] + mdeg * nz[1] + moth * nz[2];
        float inv = (plen > 0) ? (1.0f / (float)plen) : 0.0f;
        W[idx][0] = (float)msim * inv;
        W[idx][1] = (float)mdeg * inv;
        W[idx][2] = (float)moth * inv;
        float4 dl;
        dl.x = W[idx][0]*P[0].x + W[idx][1]*P[1].x + W[idx][2]*P[2].x;
        dl.y = W[idx][0]*P[0].y + W[idx][1]*P[1].y + W[idx][2]*P[2].y;
        dl.z = W[idx][0]*P[0].z + W[idx][1]*P[1].z + W[idx][2]*P[2].z;
        dl.w = W[idx][0]*P[0].w + W[idx][1]*P[1].w + W[idx][2]*P[2].w;
        g_delta[idx][lane] = dl;
    }
    if (lane == 0) {
        for (int idx = 0; idx < 4; idx++) {
            g_W[idx][0] = W[idx][0]; g_W[idx][1] = W[idx][1];
            g_W[idx][2] = W[idx][2]; g_W[idx][3] = 0.f;
            for (int k = 0; k < 3; k++)
                g_GV[idx][k] = G[k][0]*W[idx][0] + G[k][1]*W[idx][1] + G[k][2]*W[idx][2];
            g_GV[idx][3] = 0.f;
        }
        for (int a = 0; a < 4; a++)
            for (int b = 0; b < 4; b++) {
                float s = 0.f;
                for (int k = 0; k < 3; k++)
                    for (int j = 0; j < 3; j++)
                        s += W[a][k] * G[k][j] * W[b][j];
                g_GC[a][b] = s;
            }
    }
}

// ---------- K1: edges (dot + row-r norm + dense float atomics) | setup | node stats ----------
__global__ void big_kernel(const float* __restrict__ x,
                           const int* __restrict__ ei,
                           const float* __restrict__ ps,
                           const float* __restrict__ pd,
                           const float* __restrict__ po,
                           int n, int E) {
    const float4* X = reinterpret_cast<const float4*>(x);
    int bid = blockIdx.x;
    if (bid < NBE) {
        int sub     = threadIdx.x & 7;
        int group   = bid * 32 + (threadIdx.x >> 3);
        int ngroups = NBE * 32;

        int e = group;
        int r = 0, c = 0;
        if (e < E) { r = __ldg(&ei[e]); c = __ldg(&ei[E + e]); }
        while (e < E) {
            const float4* Ar = X + (size_t)r * D4 + sub;
            const float4* Bc = X + (size_t)c * D4 + sub;
            float4 a[4], b[4];
            #pragma unroll
            for (int k = 0; k < 4; k++) a[k] = __ldg(Ar + 8 * k);
            #pragma unroll
            for (int k = 0; k < 4; k++) b[k] = __ldg(Bc + 8 * k);

            int en = e + ngroups;
            int rn = 0, cn = 0;
            if (en < E) { rn = __ldg(&ei[en]); cn = __ldg(&ei[E + en]); }

            float s = 0.f, nr = 0.f;
            #pragma unroll
            for (int k = 0; k < 4; k++) {
                s  += a[k].x*b[k].x + a[k].y*b[k].y + a[k].z*b[k].z + a[k].w*b[k].w;
                nr += a[k].x*a[k].x + a[k].y*a[k].y + a[k].z*a[k].z + a[k].w*a[k].w;
            }
            #pragma unroll
            for (int o = 4; o > 0; o >>= 1) {
                s  += __shfl_xor_sync(0xFFFFFFFFu, s,  o);
                nr += __shfl_xor_sync(0xFFFFFFFFu, nr, o);
            }
            if (sub == 0) {
                g_dot[e] = s;
                atomicAdd(&g_cd[c].x, s * rsqrtf(nr));
                atomicAdd(&g_cd[c].y, 1.0f);
            }
            e = en; r = rn; c = cn;
        }
    } else if (bid == NBE) {
        if (threadIdx.x < 32) setup_body(ps, pd, po, threadIdx.x);
    } else {
        int w    = ((bid - NBE - 1) * blockDim.x + threadIdx.x) >> 5;
        int lane = threadIdx.x & 31;
        if (w >= n) return;
        float4 xv = X[(size_t)w * D4 + lane];
        float4 P0 = reinterpret_cast<const float4*>(ps)[lane];
        float4 P1 = reinterpret_cast<const float4*>(pd)[lane];
        float4 P2 = reinterpret_cast<const float4*>(po)[lane];

        float ss = xv.x*xv.x + xv.y*xv.y + xv.z*xv.z + xv.w*xv.w;
        float d0 = xv.x*P0.x + xv.y*P0.y + xv.z*P0.z + xv.w*P0.w;
        float d1 = xv.x*P1.x + xv.y*P1.y + xv.z*P1.z + xv.w*P1.w;
        float d2 = xv.x*P2.x + xv.y*P2.y + xv.z*P2.z + xv.w*P2.w;
        #pragma unroll
        for (int o = 16; o > 0; o >>= 1) {
            ss += __shfl_xor_sync(0xFFFFFFFFu, ss, o);
            d0 += __shfl_xor_sync(0xFFFFFFFFu, d0, o);
            d1 += __shfl_xor_sync(0xFFFFFFFFu, d1, o);
            d2 += __shfl_xor_sync(0xFFFFFFFFu, d2, o);
        }
        if (lane == 0) g_A0[w] = make_float4(d0, d1, d2, ss);
    }
}

// ---------- combo2 (thread/node): fold combo + norms into 16B record ----------
__global__ void combo2_kernel(int n) {
    int i = blockIdx.x * blockDim.x + threadIdx.x;
    if (i >= n) return;
    float2 cd = g_cd[i];       // (SUM(dot*rinv_r), deg)
    float4 A  = g_A0[i];       // (d0, d1, d2, ||x||^2)

    float rinv_c = rsqrtf(A.w);
    float csum = cd.x * rinv_c;
    float deg  = cd.y;

    bool msim = (deg > 0.f) && ((csum / deg) <= SIM_THR);
    bool mdeg = (deg <= DEG_THR);
    int c = (int)msim | ((int)mdeg << 1);

    float4 Wc = *reinterpret_cast<const float4*>(&g_W[c][0]);
    float4 Gv = *reinterpret_cast<const float4*>(&g_GV[c][0]);
    float xdd = Wc.x*A.x + Wc.y*A.y + Wc.z*A.z;
    float nn2 = A.w + 2.0f * xdd + g_GC[c][c];
    float s = 1.0f / fmaxf(sqrtf(fmaxf(nn2, 0.f)), EPSV);

    unsigned su = (__float_as_uint(s) & ~3u) | (unsigned)c;
    float sp = __uint_as_float(su);

    g_rec16[i] = make_float4(sp * (A.x + 0.5f * Gv.x),
                             sp * (A.y + 0.5f * Gv.y),
                             sp * (A.z + 0.5f * Gv.z), sp);
}

// ---------- K3 finish: node write (MLP4, re-zeroes g_cd) | edge2 ----------
__global__ void finish_kernel(const float* __restrict__ x,
                              const int* __restrict__ ei,
                              float* __restrict__ out,
                              float* __restrict__ keep,
                              int n, int E, int NBn) {
    if ((int)blockIdx.x < NBn) {
        int tid  = threadIdx.x;
        int node = blockIdx.x * 32 + (tid >> 3);
        if (node >= n) return;
        int j = tid & 7;
        int idx = (int)(__float_as_uint(g_rec16[node].w) & 3u);
        const float4* Xr = reinterpret_cast<const float4*>(x) + (size_t)node * D4;
        float4 xv0 = __ldcs(Xr + j);
        float4 xv1 = __ldcs(Xr + j + 8);
        float4 xv2 = __ldcs(Xr + j + 16);
        float4 xv3 = __ldcs(Xr + j + 24);
        float4 dl0 = g_delta[idx][j];
        float4 dl1 = g_delta[idx][j + 8];
        float4 dl2 = g_delta[idx][j + 16];
        float4 dl3 = g_delta[idx][j + 24];
        xv0.x += dl0.x; xv0.y += dl0.y; xv0.z += dl0.z; xv0.w += dl0.w;
        xv1.x += dl1.x; xv1.y += dl1.y; xv1.z += dl1.z; xv1.w += dl1.w;
        xv2.x += dl2.x; xv2.y += dl2.y; xv2.z += dl2.z; xv2.w += dl2.w;
        xv3.x += dl3.x; xv3.y += dl3.y; xv3.z += dl3.z; xv3.w += dl3.w;
        float4* Or = reinterpret_cast<float4*>(out) + (size_t)node * D4;
        __stcs(Or + j,      xv0);
        __stcs(Or + j + 8,  xv1);
        __stcs(Or + j + 16, xv2);
        __stcs(Or + j + 24, xv3);
        // re-zero scatter accumulator for the next graph replay (replaces memset)
        if (j == 0) g_cd[node] = make_float2(0.f, 0.f);
    } else {
        // ---- edge2: 2 edges/thread; one 16B record per endpoint ----
        int t  = (blockIdx.x - NBn) * blockDim.x + threadIdx.x;
        int e0 = t * 2;
        int e1 = e0 + 1;
        if (e0 >= E) return;
        bool has1 = (e1 < E);

        int r0 = __ldg(&ei[e0]);
        int c0 = __ldg(&ei[E + e0]);
        int r1 = has1 ? __ldg(&ei[e1]) : r0;
        int c1 = has1 ? __ldg(&ei[E + e1]) : c0;
        float dt0 = g_dot[e0];
        float dt1 = has1 ? g_dot[e1] : 0.f;

        float4 R0 = g_rec16[r0], C0 = g_rec16[c0];
        float4 R1 = g_rec16[r1], C1 = g_rec16[c1];

        int cr0 = (int)(__float_as_uint(R0.w) & 3u);
        int cc0 = (int)(__float_as_uint(C0.w) & 3u);
        int cr1 = (int)(__float_as_uint(R1.w) & 3u);
        int cc1 = (int)(__float_as_uint(C1.w) & 3u);

        float4 Wr0 = *reinterpret_cast<const float4*>(&g_W[cr0][0]);
        float4 Wc0 = *reinterpret_cast<const float4*>(&g_W[cc0][0]);
        float4 Wr1 = *reinterpret_cast<const float4*>(&g_W[cr1][0]);
        float4 Wc1 = *reinterpret_cast<const float4*>(&g_W[cc1][0]);

        float cos0 = (R0.w * C0.w) * dt0
                   + C0.w * (R0.x*Wc0.x + R0.y*Wc0.y + R0.z*Wc0.z)
                   + R0.w * (C0.x*Wr0.x + C0.y*Wr0.y + C0.z*Wr0.z);
        keep[e0] = (cos0 >= PT_THR) ? 1.0f : 0.0f;
        if (has1) {
            float cos1 = (R1.w * C1.w) * dt1
                       + C1.w * (R1.x*Wc1.x + R1.y*Wc1.y + R1.z*Wc1.z)
                       + R1.w * (C1.x*Wr1.x + C1.y*Wr1.y + C1.z*Wr1.z);
            keep[e1] = (cos1 >= PT_THR) ? 1.0f : 0.0f;
        }
    }
}

extern "C" void kernel_launch(void* const* d_in, const int* in_sizes, int n_in,
                              void* d_out, int out_size) {
    const float* x  = (const float*)d_in[0];
    const int*   ei = (const int*)d_in[1];
    const float* ps = (const float*)d_in[2];
    const float* pd = (const float*)d_in[3];
    const float* po = (const float*)d_in[4];
    float* out = (float*)d_out;

    int N = in_sizes[0] / D;
    int E = in_sizes[1] / 2;

    int NBa = (N + 7) / 8;
    big_kernel<<<NBE + 1 + NBa, 256>>>(x, ei, ps, pd, po, N, E);

    combo2_kernel<<<(N + 255) / 256, 256>>>(N);

    int NBn = (N + 31) / 32;
    bool do_keep = ((long long)out_size >= (long long)N * D + E);
    int NBe2 = do_keep ? ((E + 1) / 2 + 255) / 256 : 0;
    float* keep = out + (size_t)N * D;
    finish_kernel<<<NBn + NBe2, 256>>>(x, ei, out, keep, N, E, NBn);
}